// round 1
// baseline (speedup 1.0000x reference)
#include <cuda_runtime.h>
#include <cstdint>

#define HN 10

typedef unsigned long long ull;

// ---------- packed f32x2 helpers (sm_103a) ----------
__device__ __forceinline__ ull pk2(float a, float b){
    ull r; asm("mov.b64 %0, {%1,%2};" : "=l"(r) : "f"(a), "f"(b)); return r;
}
__device__ __forceinline__ void upk2(ull v, float& a, float& b){
    asm("mov.b64 {%0,%1}, %2;" : "=f"(a), "=f"(b) : "l"(v));
}
__device__ __forceinline__ ull fma2(ull a, ull b, ull c){
    ull d; asm("fma.rn.f32x2 %0, %1, %2, %3;" : "=l"(d) : "l"(a), "l"(b), "l"(c)); return d;
}
__device__ __forceinline__ ull mul2(ull a, ull b){
    ull d; asm("mul.rn.f32x2 %0, %1, %2;" : "=l"(d) : "l"(a), "l"(b)); return d;
}
__device__ __forceinline__ ull add2(ull a, ull b){
    ull d; asm("add.rn.f32x2 %0, %1, %2;" : "=l"(d) : "l"(a), "l"(b)); return d;
}
__device__ __forceinline__ ull neg2(ull a){ return a ^ 0x8000000080000000ULL; }

// accurate-enough tanh: 1 - 2/(exp(2z)+1). abs err ~1e-6, saturates cleanly.
__device__ __forceinline__ float tanh1(float z){
    float e = __expf(2.0f * z);
    return 1.0f - __fdividef(2.0f, e + 1.0f);
}
__device__ __forceinline__ ull tanh2v(ull v){
    float a, b; upk2(v, a, b);
    return pk2(tanh1(a), tanh1(b));
}

__global__ void __launch_bounds__(128)
pinn_kernel(const float* __restrict__ x,
            const float* __restrict__ W1, const float* __restrict__ b1,
            const float* __restrict__ W2, const float* __restrict__ b2,
            const float* __restrict__ W3, const float* __restrict__ b3,
            const float* __restrict__ W4,
            float* __restrict__ out, int n)
{
    // weights pre-duplicated as (w,w) 64-bit pairs for direct FFMA2 operands
    __shared__ __align__(16) ull sW2[HN*HN], sW3[HN*HN];
    __shared__ __align__(16) ull sW1[HN], sB1[HN], sB2[HN], sB3[HN], sW4[HN];

    int t = threadIdx.x;
    if (t < HN*HN){
        float w = W2[t]; sW2[t] = pk2(w, w);
        w = W3[t];       sW3[t] = pk2(w, w);
    }
    if (t < HN){
        float w;
        w = W1[t]; sW1[t] = pk2(w, w);
        w = b1[t]; sB1[t] = pk2(w, w);
        w = b2[t]; sB2[t] = pk2(w, w);
        w = b3[t]; sB3[t] = pk2(w, w);
        w = W4[t]; sW4[t] = pk2(w, w);
    }
    __syncthreads();

    int i0 = (blockIdx.x * blockDim.x + threadIdx.x) * 2;   // 2 points per thread
    if (i0 >= n) return;
    float x0 = x[i0];
    float x1 = (i0 + 1 < n) ? x[i0 + 1] : 0.0f;
    ull xp = pk2(x0, x1);
    const ull ONE2 = 0x3f8000003f800000ULL;

    ull h[HN], hp[HN], hpp[HN];

    // ----- layer 1: z = x*W1 + b1 (scalar input) -----
    #pragma unroll
    for (int j = 0; j < HN; j++){
        ull w  = sW1[j];
        ull z  = fma2(xp, w, sB1[j]);
        ull tt = tanh2v(z);
        ull s  = fma2(neg2(tt), tt, ONE2);      // s = 1 - t^2
        h[j]   = tt;
        ull hpj = mul2(s, w);                   // h' = s*W1
        hp[j]  = hpj;
        ull m  = mul2(tt, hpj);                 // t*s*W1
        m      = add2(m, m);                    // 2*t*s*W1
        hpp[j] = neg2(mul2(m, w));              // h'' = -2*t*s*W1^2
    }

    // ----- layers 2 and 3: z = h@W + b, z' = h'@W, z'' = h''@W -----
    #pragma unroll
    for (int layer = 0; layer < 2; layer++){
        const ull* Wd = (layer == 0) ? sW2 : sW3;
        const ull* Bd = (layer == 0) ? sB2 : sB3;
        ull z[HN], zp[HN], zpp[HN];
        #pragma unroll
        for (int j = 0; j < HN; j++){ z[j] = Bd[j]; zp[j] = 0ULL; zpp[j] = 0ULL; }
        #pragma unroll
        for (int i = 0; i < HN; i++){
            ull hi = h[i], hpi = hp[i], hppi = hpp[i];
            #pragma unroll
            for (int j = 0; j < HN; j++){
                ull w  = Wd[i*HN + j];          // broadcast LDS, reused for 3 FFMA2
                z[j]   = fma2(hi,   w, z[j]);
                zp[j]  = fma2(hpi,  w, zp[j]);
                zpp[j] = fma2(hppi, w, zpp[j]);
            }
        }
        #pragma unroll
        for (int j = 0; j < HN; j++){
            ull tt = tanh2v(z[j]);
            ull s  = fma2(neg2(tt), tt, ONE2);  // s = 1 - t^2
            h[j]   = tt;
            ull hpn = mul2(s, zp[j]);           // h' = s*z'
            ull m   = mul2(tt, zp[j]);
            m       = add2(m, m);               // 2*t*z'
            // h'' = s*z'' - 2*t*z' * (s*z')
            hpp[j] = fma2(neg2(m), hpn, mul2(s, zpp[j]));
            hp[j]  = hpn;
        }
    }

    // ----- output: dot with W4 (no bias) -----
    ull u = 0ULL, ux = 0ULL, uxx = 0ULL;
    #pragma unroll
    for (int j = 0; j < HN; j++){
        ull w = sW4[j];
        u   = fma2(h[j],   w, u);
        ux  = fma2(hp[j],  w, ux);
        uxx = fma2(hpp[j], w, uxx);
    }

    float ua, ub, da, db, ca, cb;
    upk2(u, ua, ub); upk2(ux, da, db); upk2(uxx, ca, cb);
    float* o = out + (size_t)3 * i0;
    if (i0 + 1 < n){
        float2* o2 = (float2*)o;                // 3*i0 even -> 8B aligned
        o2[0] = make_float2(ua, da);
        o2[1] = make_float2(ca, ub);
        o2[2] = make_float2(db, cb);
    } else {
        o[0] = ua; o[1] = da; o[2] = ca;
    }
}

extern "C" void kernel_launch(void* const* d_in, const int* in_sizes, int n_in,
                              void* d_out, int out_size)
{
    const float* x  = (const float*)d_in[0];
    const float* W1 = (const float*)d_in[1];
    const float* b1 = (const float*)d_in[2];
    const float* W2 = (const float*)d_in[3];
    const float* b2 = (const float*)d_in[4];
    const float* W3 = (const float*)d_in[5];
    const float* b3 = (const float*)d_in[6];
    const float* W4 = (const float*)d_in[7];
    float* out = (float*)d_out;

    int n = in_sizes[0];
    const int threads = 128;
    const int pts_per_block = threads * 2;
    int blocks = (n + pts_per_block - 1) / pts_per_block;
    pinn_kernel<<<blocks, threads>>>(x, W1, b1, W2, b2, W3, b3, W4, out, n);
}